// round 16
// baseline (speedup 1.0000x reference)
#include <cuda_runtime.h>
#include <math.h>
#include <stdint.h>

// ---------------------------------------------------------------------------
// MiniGPT forward, fp32 SIMT implementation.
// B=4, T=1024, D=768, H=12, hd=64, L=4, DFF=3072, V=32000.
// ---------------------------------------------------------------------------

#define D_MODEL 768
#define NHEAD   12
#define HD      64
#define TSEQ    1024
#define BATCH   4
#define NROWS   (BATCH * TSEQ)   // 4096
#define DFF_    3072
#define VOCAB   32000
#define NLAYER  4

// Scratch (device globals: no runtime allocation allowed)
__device__ float g_x  [NROWS * D_MODEL];
__device__ float g_xn [NROWS * D_MODEL];
__device__ float g_q  [NROWS * D_MODEL];
__device__ float g_k  [NROWS * D_MODEL];
__device__ float g_v  [NROWS * D_MODEL];
__device__ float g_att[NROWS * D_MODEL];
__device__ float g_h1 [NROWS * DFF_];

// ---------------------------------------------------------------------------
// Embedding: x[r, c] = tok_emb[idx[r], c] + pos_emb[r % T, c]
// ---------------------------------------------------------------------------
__global__ __launch_bounds__(256) void embed_kernel(
    const int* __restrict__ idx, const float* __restrict__ tok,
    const float* __restrict__ pos, float* __restrict__ x)
{
    int r = blockIdx.x;
    int t = r & (TSEQ - 1);
    int token = idx[r];
    const float* tr = tok + (size_t)token * D_MODEL;
    const float* pr = pos + (size_t)t * D_MODEL;
    float* xr = x + (size_t)r * D_MODEL;
    for (int c = threadIdx.x; c < D_MODEL; c += 256)
        xr[c] = tr[c] + pr[c];
}

// ---------------------------------------------------------------------------
// LayerNorm: one block (256 threads) per row of 768
// ---------------------------------------------------------------------------
__global__ __launch_bounds__(256) void ln_kernel(
    const float* __restrict__ x, const float* __restrict__ g,
    const float* __restrict__ b, float* __restrict__ y)
{
    const int r = blockIdx.x;
    const int tid = threadIdx.x;
    const float* xr = x + (size_t)r * D_MODEL;

    float v0 = xr[tid], v1 = xr[tid + 256], v2 = xr[tid + 512];
    float s  = v0 + v1 + v2;
    float sq = v0*v0 + v1*v1 + v2*v2;
#pragma unroll
    for (int off = 16; off; off >>= 1) {
        s  += __shfl_xor_sync(0xffffffffu, s,  off);
        sq += __shfl_xor_sync(0xffffffffu, sq, off);
    }
    __shared__ float ss[8], ssq[8], stat[2];
    int w = tid >> 5, lane = tid & 31;
    if (lane == 0) { ss[w] = s; ssq[w] = sq; }
    __syncthreads();
    if (tid == 0) {
        float S = 0.f, SQ = 0.f;
#pragma unroll
        for (int i = 0; i < 8; i++) { S += ss[i]; SQ += ssq[i]; }
        float mean = S * (1.0f / (float)D_MODEL);
        float var  = SQ * (1.0f / (float)D_MODEL) - mean * mean;
        stat[0] = mean;
        stat[1] = rsqrtf(var + 1e-5f);
    }
    __syncthreads();
    float mean = stat[0], rstd = stat[1];
    float* yr = y + (size_t)r * D_MODEL;
    yr[tid]       = (v0 - mean) * rstd * g[tid]       + b[tid];
    yr[tid + 256] = (v1 - mean) * rstd * g[tid + 256] + b[tid + 256];
    yr[tid + 512] = (v2 - mean) * rstd * g[tid + 512] + b[tid + 512];
}

// ---------------------------------------------------------------------------
// SGEMM: C[M,N] = A[M,K] @ B[K,N]  (+bias)(+relu)(+residual)
// 128x128x16 tiles, 256 threads, 8x8 fragments, A-tile stored transposed.
// M,N,K all divisible by 128/128/16 in this problem (checked: 4096/768/3072/32000).
// ---------------------------------------------------------------------------
template<bool RELU, bool RES, bool BIAS>
__global__ __launch_bounds__(256) void sgemm_kernel(
    const float* __restrict__ A, const float* __restrict__ B,
    const float* __restrict__ bias, const float* __restrict__ res,
    float* __restrict__ C, int M, int N, int K)
{
    __shared__ float As[16][128];   // As[k][m]
    __shared__ float Bs[16][128];   // Bs[k][n]

    const int tid = threadIdx.x;
    const int bx = blockIdx.x;      // N tiles
    const int by = blockIdx.y;      // M tiles
    const int tx = tid & 15, ty = tid >> 4;
    const int row0 = ty * 8, col0 = tx * 8;

    const float* Ablk = A + (size_t)by * 128 * K;
    const float* Bblk = B + (size_t)bx * 128;

    float acc[8][8];
#pragma unroll
    for (int i = 0; i < 8; i++)
#pragma unroll
        for (int j = 0; j < 8; j++) acc[i][j] = 0.f;

    for (int kt = 0; kt < K; kt += 16) {
#pragma unroll
        for (int u = 0; u < 2; u++) {
            int f = tid + u * 256;
            // A tile: 128 rows x 16 cols, write transposed
            int ar = f >> 2;
            int ak = (f & 3) << 2;
            float4 av = *(const float4*)(Ablk + (size_t)ar * K + kt + ak);
            As[ak + 0][ar] = av.x;
            As[ak + 1][ar] = av.y;
            As[ak + 2][ar] = av.z;
            As[ak + 3][ar] = av.w;
            // B tile: 16 rows x 128 cols, direct
            int br = f >> 5;
            int bc = (f & 31) << 2;
            *(float4*)(&Bs[br][bc]) =
                *(const float4*)(Bblk + (size_t)(kt + br) * N + bc);
        }
        __syncthreads();
#pragma unroll
        for (int k = 0; k < 16; k++) {
            float a[8], bfr[8];
            *(float4*)(a)     = *(const float4*)(&As[k][row0]);
            *(float4*)(a + 4) = *(const float4*)(&As[k][row0 + 4]);
            *(float4*)(bfr)     = *(const float4*)(&Bs[k][col0]);
            *(float4*)(bfr + 4) = *(const float4*)(&Bs[k][col0 + 4]);
#pragma unroll
            for (int i = 0; i < 8; i++)
#pragma unroll
                for (int j = 0; j < 8; j++)
                    acc[i][j] += a[i] * bfr[j];
        }
        __syncthreads();
    }

    // Epilogue
    const int gc0 = bx * 128 + col0;
    float bval[8];
    if (BIAS) {
#pragma unroll
        for (int j = 0; j < 8; j++) bval[j] = bias[gc0 + j];
    }
#pragma unroll
    for (int i = 0; i < 8; i++) {
        size_t gr = (size_t)(by * 128 + row0 + i);
        float out[8];
#pragma unroll
        for (int j = 0; j < 8; j++) {
            float vv = acc[i][j];
            if (BIAS) vv += bval[j];
            if (RELU) vv = fmaxf(vv, 0.f);
            out[j] = vv;
        }
        if (RES) {
            float4 r0v = *(const float4*)(res + gr * N + gc0);
            float4 r1v = *(const float4*)(res + gr * N + gc0 + 4);
            out[0] += r0v.x; out[1] += r0v.y; out[2] += r0v.z; out[3] += r0v.w;
            out[4] += r1v.x; out[5] += r1v.y; out[6] += r1v.z; out[7] += r1v.w;
        }
        *(float4*)(C + gr * N + gc0)     = make_float4(out[0], out[1], out[2], out[3]);
        *(float4*)(C + gr * N + gc0 + 4) = make_float4(out[4], out[5], out[6], out[7]);
    }
}

// ---------------------------------------------------------------------------
// Flash attention: one block per (q-tile of 64, head, batch). 256 threads as
// 16x16, each owning a 4x4 fragment of the 64x64 S / O tiles. Online softmax;
// O and row stats live in registers (replicated across the 16 lanes of a row
// group — shfl-16 reductions keep them coherent).
// ---------------------------------------------------------------------------
#define ATTN_SMEM ((64*68 + 64*64 + 64*68 + 64*68) * 4)

__global__ __launch_bounds__(256) void attn_kernel(
    const float* __restrict__ q, const float* __restrict__ k,
    const float* __restrict__ v, float* __restrict__ out)
{
    extern __shared__ float sm[];
    float* Qs = sm;                 // [64][68]  Qs[r*68+d], pre-scaled by 1/8
    float* Kt = Qs + 64 * 68;       // [64][64]  Kt[d*64+c]
    float* Vs = Kt + 64 * 64;       // [64][68]  Vs[s*68+d]
    float* Ps = Vs + 64 * 68;       // [64][68]  Ps[r*68+s]

    const int qt = blockIdx.x;
    const int h  = blockIdx.y;
    const int b  = blockIdx.z;
    const int tid = threadIdx.x;
    const int tx = tid & 15, ty = tid >> 4;
    const int r0 = ty * 4, c0 = tx * 4;
    const size_t rowBase = (size_t)b * TSEQ;
    const int colOff = h * HD;

    // Load Q tile (scaled by hd^-0.5 = 0.125)
#pragma unroll
    for (int f = tid; f < 1024; f += 256) {
        int r = f >> 4, d4 = (f & 15) << 2;
        float4 t4 = *(const float4*)(q + (rowBase + qt * 64 + r) * D_MODEL + colOff + d4);
        *(float4*)(Qs + r * 68 + d4) =
            make_float4(t4.x * 0.125f, t4.y * 0.125f, t4.z * 0.125f, t4.w * 0.125f);
    }

    float o[4][4];
#pragma unroll
    for (int i = 0; i < 4; i++)
#pragma unroll
        for (int j = 0; j < 4; j++) o[i][j] = 0.f;
    float m_i[4] = {-1e30f, -1e30f, -1e30f, -1e30f};
    float l_i[4] = {0.f, 0.f, 0.f, 0.f};

    for (int kt = 0; kt <= qt; kt++) {
        __syncthreads();   // previous iteration fully done before smem reuse
        // K tile, transposed (r-fast thread mapping => conflict-free STS)
#pragma unroll
        for (int f = tid; f < 1024; f += 256) {
            int r = f & 63, d4 = (f >> 6) << 2;
            const float* kp = k + (rowBase + kt * 64 + r) * D_MODEL + colOff + d4;
            Kt[(d4 + 0) * 64 + r] = kp[0];
            Kt[(d4 + 1) * 64 + r] = kp[1];
            Kt[(d4 + 2) * 64 + r] = kp[2];
            Kt[(d4 + 3) * 64 + r] = kp[3];
        }
        // V tile, natural layout
#pragma unroll
        for (int f = tid; f < 1024; f += 256) {
            int r = f >> 4, d4 = (f & 15) << 2;
            *(float4*)(Vs + r * 68 + d4) =
                *(const float4*)(v + (rowBase + kt * 64 + r) * D_MODEL + colOff + d4);
        }
        __syncthreads();

        // S = Q @ K^T (already scaled)
        float s[4][4];
#pragma unroll
        for (int i = 0; i < 4; i++)
#pragma unroll
            for (int j = 0; j < 4; j++) s[i][j] = 0.f;
#pragma unroll 8
        for (int d = 0; d < 64; d++) {
            float a0 = Qs[(r0 + 0) * 68 + d];
            float a1 = Qs[(r0 + 1) * 68 + d];
            float a2 = Qs[(r0 + 2) * 68 + d];
            float a3 = Qs[(r0 + 3) * 68 + d];
            float4 bb = *(const float4*)(Kt + d * 64 + c0);
            s[0][0] += a0 * bb.x; s[0][1] += a0 * bb.y; s[0][2] += a0 * bb.z; s[0][3] += a0 * bb.w;
            s[1][0] += a1 * bb.x; s[1][1] += a1 * bb.y; s[1][2] += a1 * bb.z; s[1][3] += a1 * bb.w;
            s[2][0] += a2 * bb.x; s[2][1] += a2 * bb.y; s[2][2] += a2 * bb.z; s[2][3] += a2 * bb.w;
            s[3][0] += a3 * bb.x; s[3][1] += a3 * bb.y; s[3][2] += a3 * bb.z; s[3][3] += a3 * bb.w;
        }
        if (kt == qt) {   // causal mask on the diagonal tile
#pragma unroll
            for (int i = 0; i < 4; i++)
#pragma unroll
                for (int j = 0; j < 4; j++)
                    if (c0 + j > r0 + i) s[i][j] = -1e30f;
        }

        // Online softmax (per-row stats replicated across the 16-lane row group)
#pragma unroll
        for (int i = 0; i < 4; i++) {
            float mx = fmaxf(fmaxf(s[i][0], s[i][1]), fmaxf(s[i][2], s[i][3]));
            mx = fmaxf(mx, __shfl_xor_sync(0xffffffffu, mx, 8));
            mx = fmaxf(mx, __shfl_xor_sync(0xffffffffu, mx, 4));
            mx = fmaxf(mx, __shfl_xor_sync(0xffffffffu, mx, 2));
            mx = fmaxf(mx, __shfl_xor_sync(0xffffffffu, mx, 1));
            float mn    = fmaxf(m_i[i], mx);
            float alpha = __expf(m_i[i] - mn);
            m_i[i] = mn;
            float p0 = __expf(s[i][0] - mn);
            float p1 = __expf(s[i][1] - mn);
            float p2 = __expf(s[i][2] - mn);
            float p3 = __expf(s[i][3] - mn);
            float rs = p0 + p1 + p2 + p3;
            rs += __shfl_xor_sync(0xffffffffu, rs, 8);
            rs += __shfl_xor_sync(0xffffffffu, rs, 4);
            rs += __shfl_xor_sync(0xffffffffu, rs, 2);
            rs += __shfl_xor_sync(0xffffffffu, rs, 1);
            l_i[i] = l_i[i] * alpha + rs;
            o[i][0] *= alpha; o[i][1] *= alpha; o[i][2] *= alpha; o[i][3] *= alpha;
            Ps[(r0 + i) * 68 + c0 + 0] = p0;
            Ps[(r0 + i) * 68 + c0 + 1] = p1;
            Ps[(r0 + i) * 68 + c0 + 2] = p2;
            Ps[(r0 + i) * 68 + c0 + 3] = p3;
        }
        __syncthreads();

        // O += P @ V
#pragma unroll 8
        for (int sidx = 0; sidx < 64; sidx++) {
            float a0 = Ps[(r0 + 0) * 68 + sidx];
            float a1 = Ps[(r0 + 1) * 68 + sidx];
            float a2 = Ps[(r0 + 2) * 68 + sidx];
            float a3 = Ps[(r0 + 3) * 68 + sidx];
            float4 bb = *(const float4*)(Vs + sidx * 68 + c0);
            o[0][0] += a0 * bb.x; o[0][1] += a0 * bb.y; o[0][2] += a0 * bb.z; o[0][3] += a0 * bb.w;
            o[1][0] += a1 * bb.x; o[1][1] += a1 * bb.y; o[1][2] += a1 * bb.z; o[1][3] += a1 * bb.w;
            o[2][0] += a2 * bb.x; o[2][1] += a2 * bb.y; o[2][2] += a2 * bb.z; o[2][3] += a2 * bb.w;
            o[3][0] += a3 * bb.x; o[3][1] += a3 * bb.y; o[3][2] += a3 * bb.z; o[3][3] += a3 * bb.w;
        }
    }

#pragma unroll
    for (int i = 0; i < 4; i++) {
        float inv = 1.0f / l_i[i];
        *(float4*)(out + (rowBase + qt * 64 + r0 + i) * D_MODEL + colOff + c0) =
            make_float4(o[i][0] * inv, o[i][1] * inv, o[i][2] * inv, o[i][3] * inv);
    }
}

// ---------------------------------------------------------------------------
// kernel_launch
// ---------------------------------------------------------------------------
extern "C" void kernel_launch(void* const* d_in, const int* in_sizes, int n_in,
                              void* d_out, int out_size)
{
    const int*   idx   = (const int*)  d_in[0];
    const float* tok   = (const float*)d_in[1];
    const float* pos   = (const float*)d_in[2];
    const float* Wq    = (const float*)d_in[3];
    const float* Wk    = (const float*)d_in[4];
    const float* Wv    = (const float*)d_in[5];
    const float* Wproj = (const float*)d_in[6];
    const float* bproj = (const float*)d_in[7];
    const float* ln1g  = (const float*)d_in[8];
    const float* ln1b  = (const float*)d_in[9];
    const float* ln2g  = (const float*)d_in[10];
    const float* ln2b  = (const float*)d_in[11];
    const float* W1    = (const float*)d_in[12];
    const float* b1    = (const float*)d_in[13];
    const float* W2    = (const float*)d_in[14];
    const float* b2    = (const float*)d_in[15];
    const float* lnfg  = (const float*)d_in[16];
    const float* lnfb  = (const float*)d_in[17];
    const float* Wlm   = (const float*)d_in[18];
    const float* blm   = (const float*)d_in[19];
    float* out = (float*)d_out;

    float *x, *xn, *q, *k, *v, *att, *h1;
    cudaGetSymbolAddress((void**)&x,   g_x);
    cudaGetSymbolAddress((void**)&xn,  g_xn);
    cudaGetSymbolAddress((void**)&q,   g_q);
    cudaGetSymbolAddress((void**)&k,   g_k);
    cudaGetSymbolAddress((void**)&v,   g_v);
    cudaGetSymbolAddress((void**)&att, g_att);
    cudaGetSymbolAddress((void**)&h1,  g_h1);

    cudaFuncSetAttribute(attn_kernel,
                         cudaFuncAttributeMaxDynamicSharedMemorySize, ATTN_SMEM);

    embed_kernel<<<NROWS, 256>>>(idx, tok, pos, x);

    const dim3 gDD(D_MODEL / 128, NROWS / 128);   // (6, 32)
    const dim3 gFF1(DFF_ / 128, NROWS / 128);     // (24, 32)
    const dim3 gAT(TSEQ / 64, NHEAD, BATCH);      // (16, 12, 4)

    for (int l = 0; l < NLAYER; l++) {
        const size_t wOff  = (size_t)l * D_MODEL * D_MODEL;
        const size_t dOff  = (size_t)l * D_MODEL;
        const size_t w1Off = (size_t)l * D_MODEL * DFF_;
        const size_t w2Off = (size_t)l * DFF_ * D_MODEL;
        const size_t fOff  = (size_t)l * DFF_;

        ln_kernel<<<NROWS, 256>>>(x, ln1g + dOff, ln1b + dOff, xn);

        sgemm_kernel<false, false, false><<<gDD, 256>>>(
            xn, Wq + wOff, nullptr, nullptr, q, NROWS, D_MODEL, D_MODEL);
        sgemm_kernel<false, false, false><<<gDD, 256>>>(
            xn, Wk + wOff, nullptr, nullptr, k, NROWS, D_MODEL, D_MODEL);
        sgemm_kernel<false, false, false><<<gDD, 256>>>(
            xn, Wv + wOff, nullptr, nullptr, v, NROWS, D_MODEL, D_MODEL);

        attn_kernel<<<gAT, 256, ATTN_SMEM>>>(q, k, v, att);

        // x = att @ Wproj + bproj + x
        sgemm_kernel<false, true, true><<<gDD, 256>>>(
            att, Wproj + wOff, bproj + dOff, x, x, NROWS, D_MODEL, D_MODEL);

        ln_kernel<<<NROWS, 256>>>(x, ln2g + dOff, ln2b + dOff, xn);

        // h1 = relu(xn @ W1 + b1)
        sgemm_kernel<true, false, true><<<gFF1, 256>>>(
            xn, W1 + w1Off, b1 + fOff, nullptr, h1, NROWS, DFF_, D_MODEL);

        // x = h1 @ W2 + b2 + x
        sgemm_kernel<false, true, true><<<gDD, 256>>>(
            h1, W2 + w2Off, b2 + dOff, x, x, NROWS, D_MODEL, DFF_);
    }

    ln_kernel<<<NROWS, 256>>>(x, lnfg, lnfb, xn);

    // logits = xn @ Wlm + blm
    const dim3 gLM(VOCAB / 128, NROWS / 128);     // (250, 32)
    sgemm_kernel<false, false, true><<<gLM, 256>>>(
        xn, Wlm, blm, nullptr, out, NROWS, VOCAB, D_MODEL);
}